// round 6
// baseline (speedup 1.0000x reference)
#include <cuda_runtime.h>
#include <cuda_bf16.h>

#define N_NODES 50000
#define N_EDGES 800000
#define D 64

// ---------------------------------------------------------------------------
// Static device scratch (allocation-guard-legal).
// g_cnt is zero at module load, and every run re-zeroes it inside scan_all
// after consuming it, so replays are deterministic.
// ---------------------------------------------------------------------------
__device__ int   g_cnt[N_NODES];
__device__ int   g_offs[N_NODES + 1];
__device__ int   g_cursor[N_NODES];
__device__ int   g_sorted[N_EDGES];
__device__ float g_neigh[N_NODES * D];

// ---------------------------------------------------------------------------
// 1) Histogram of destination degrees. Unused return value -> RED (no-return).
// ---------------------------------------------------------------------------
__global__ __launch_bounds__(256) void hist_kernel(const int* __restrict__ dst,
                                                   int* __restrict__ cnt)
{
    int e = blockIdx.x * blockDim.x + threadIdx.x;
    if (e < N_EDGES) atomicAdd(&cnt[__ldg(dst + e)], 1);
}

// ---------------------------------------------------------------------------
// 2) Full exclusive scan of 50k counters in ONE block of 1024 threads.
//    Blocked ownership (thread t owns [t*49, t*49+49)), two-level shuffle
//    scan, writes offs + cursor, and zeroes cnt for the next graph replay.
// ---------------------------------------------------------------------------
#define PER ((N_NODES + 1023) / 1024)   // 49

__global__ __launch_bounds__(1024) void scan_all_kernel(
    int* __restrict__ cnt, int* __restrict__ offs, int* __restrict__ cursor)
{
    __shared__ int wsum[32];
    const int t = threadIdx.x;
    const int warp = t >> 5, lane = t & 31;
    const int base = t * PER;

    // Pass 1: per-thread sum (loads are independent -> high MLP)
    int sum = 0;
#pragma unroll
    for (int i = 0; i < PER; i++) {
        int idx = base + i;
        if (idx < N_NODES) sum += __ldg(cnt + idx);
    }

    // Inclusive warp scan of per-thread sums
    int v = sum;
#pragma unroll
    for (int o = 1; o < 32; o <<= 1) {
        int u = __shfl_up_sync(~0u, v, o);
        if (lane >= o) v += u;
    }
    if (lane == 31) wsum[warp] = v;
    __syncthreads();

    // Warp 0 scans the 32 warp sums
    if (warp == 0) {
        int w = wsum[lane];
        int wv = w;
#pragma unroll
        for (int o = 1; o < 32; o <<= 1) {
            int u = __shfl_up_sync(~0u, wv, o);
            if (lane >= o) wv += u;
        }
        wsum[lane] = wv - w;   // exclusive warp base
    }
    __syncthreads();

    int run = wsum[warp] + v - sum;   // exclusive prefix for this thread

    // Pass 2: write offsets + cursors, zero counters (L1-resident re-reads)
#pragma unroll
    for (int i = 0; i < PER; i++) {
        int idx = base + i;
        if (idx < N_NODES) {
            int c = cnt[idx];
            offs[idx]   = run;
            cursor[idx] = run;
            cnt[idx]    = 0;        // restore for next replay
            run += c;
        }
    }
    if (t == 1023) offs[N_NODES] = run;   // = N_EDGES
}

// ---------------------------------------------------------------------------
// 3) Scatter src indices into dst-sorted order (R4-proven form)
// ---------------------------------------------------------------------------
__global__ __launch_bounds__(256) void scatter_idx_kernel(
    const int* __restrict__ src, const int* __restrict__ dst,
    int* __restrict__ cursor, int* __restrict__ sorted)
{
    int e = blockIdx.x * blockDim.x + threadIdx.x;
    if (e >= N_EDGES) return;
    int d = __ldg(dst + e);
    int pos = atomicAdd(&cursor[d], 1);
    sorted[pos] = __ldg(src + e);
}

// ---------------------------------------------------------------------------
// 4) Per-node gather-sum (PROVEN: 18.1us, at LTS cap). 16 lanes/node.
// ---------------------------------------------------------------------------
__global__ __launch_bounds__(256) void gather_kernel(
    const float4* __restrict__ feat, const int* __restrict__ offs,
    const int* __restrict__ sorted, float4* __restrict__ neigh)
{
    int g = (blockIdx.x * blockDim.x + threadIdx.x) >> 4;   // node
    int c = threadIdx.x & 15;
    if (g >= N_NODES) return;

    int beg = __ldg(offs + g);
    int end = __ldg(offs + g + 1);

    float4 a = make_float4(0.f, 0.f, 0.f, 0.f);
    int e = beg;
    for (; e + 4 <= end; e += 4) {
        int s0 = __ldg(sorted + e);
        int s1 = __ldg(sorted + e + 1);
        int s2 = __ldg(sorted + e + 2);
        int s3 = __ldg(sorted + e + 3);
        float4 f0 = feat[s0 * 16 + c];
        float4 f1 = feat[s1 * 16 + c];
        float4 f2 = feat[s2 * 16 + c];
        float4 f3 = feat[s3 * 16 + c];
        a.x += (f0.x + f1.x) + (f2.x + f3.x);
        a.y += (f0.y + f1.y) + (f2.y + f3.y);
        a.z += (f0.z + f1.z) + (f2.z + f3.z);
        a.w += (f0.w + f1.w) + (f2.w + f3.w);
    }
    for (; e < end; e++) {
        int s = __ldg(sorted + e);
        float4 f = feat[s * 16 + c];
        a.x += f.x; a.y += f.y; a.z += f.z; a.w += f.w;
    }
    neigh[g * 16 + c] = a;
}

// ---------------------------------------------------------------------------
// 5) out = ((1+eps)*feat + neigh) @ W^T + b  (R4-proven scalar-FFMA body)
// ---------------------------------------------------------------------------
#define GROWS 96

__global__ __launch_bounds__(GROWS) void gemm_kernel(
    const float4* __restrict__ feat, const float4* __restrict__ neigh,
    const float4* __restrict__ W, const float* __restrict__ b,
    const float* __restrict__ eps, float4* __restrict__ out)
{
    __shared__ float4 Wsm[64 * 16];       // Wsm[j*16 + kq] = W[j][4kq..4kq+3]
    __shared__ float4 tile[GROWS * 17];   // padded row stride: 17 float4
    __shared__ float  bsm[64];

    const int tid  = threadIdx.x;
    const int row0 = blockIdx.x * GROWS;

    for (int i = tid; i < 64 * 16; i += GROWS) Wsm[i] = W[i];
    if (tid < 64) bsm[tid] = b[tid];
    float s = 1.0f + __ldg(eps);

    for (int i = tid; i < GROWS * 16; i += GROWS) {
        int r = i >> 4, c = i & 15;
        int gr = row0 + r;
        float4 v = make_float4(0.f, 0.f, 0.f, 0.f);
        if (gr < N_NODES) {
            float4 f = feat[gr * 16 + c];
            float4 n = neigh[gr * 16 + c];
            v.x = s * f.x + n.x;
            v.y = s * f.y + n.y;
            v.z = s * f.z + n.z;
            v.w = s * f.w + n.w;
        }
        tile[r * 17 + c] = v;
    }
    __syncthreads();

    float acc[64];
#pragma unroll
    for (int j = 0; j < 64; j++) acc[j] = 0.f;

    for (int kq = 0; kq < 16; kq++) {           // NOT unrolled (I$)
        float4 v = tile[tid * 17 + kq];
#pragma unroll
        for (int j = 0; j < 64; j++) {          // broadcast LDS.128 of W
            float4 w = Wsm[j * 16 + kq];
            acc[j] += v.x * w.x + v.y * w.y + v.z * w.z + v.w * w.w;
        }
    }

#pragma unroll
    for (int j = 0; j < 64; j++) acc[j] += bsm[j];

    __syncthreads();
#pragma unroll
    for (int q = 0; q < 16; q++)
        tile[tid * 17 + q] =
            make_float4(acc[4 * q], acc[4 * q + 1], acc[4 * q + 2], acc[4 * q + 3]);
    __syncthreads();

    for (int i = tid; i < GROWS * 16; i += GROWS) {
        int r = i >> 4, c = i & 15;
        int gr = row0 + r;
        if (gr < N_NODES) out[gr * 16 + c] = tile[r * 17 + c];
    }
}

// ---------------------------------------------------------------------------
// Launch: inputs per metadata order: feat, W, b, eps, src, dst
// 5 launches total (launch floor ~4.5us each dominates small kernels).
// ---------------------------------------------------------------------------
extern "C" void kernel_launch(void* const* d_in, const int* in_sizes, int n_in,
                              void* d_out, int out_size)
{
    const float4* feat = (const float4*)d_in[0];
    const float4* W    = (const float4*)d_in[1];
    const float*  b    = (const float*)d_in[2];
    const float*  eps  = (const float*)d_in[3];
    const int*    src  = (const int*)d_in[4];
    const int*    dst  = (const int*)d_in[5];
    float4*       out  = (float4*)d_out;

    int *cnt, *offs, *cursor, *sorted;
    float* neigh;
    cudaGetSymbolAddress((void**)&cnt,    g_cnt);
    cudaGetSymbolAddress((void**)&offs,   g_offs);
    cudaGetSymbolAddress((void**)&cursor, g_cursor);
    cudaGetSymbolAddress((void**)&sorted, g_sorted);
    cudaGetSymbolAddress((void**)&neigh,  g_neigh);

    const int EB = (N_EDGES + 255) / 256;

    hist_kernel<<<EB, 256>>>(dst, cnt);
    scan_all_kernel<<<1, 1024>>>(cnt, offs, cursor);
    scatter_idx_kernel<<<EB, 256>>>(src, dst, cursor, sorted);
    {
        int threads = N_NODES * 16;
        gather_kernel<<<(threads + 255) / 256, 256>>>(feat, offs, sorted,
                                                      (float4*)neigh);
    }
    {
        int blocks = (N_NODES + GROWS - 1) / GROWS;
        gemm_kernel<<<blocks, GROWS>>>(feat, (const float4*)neigh, W, b, eps,
                                       out);
    }
}

// round 7
// speedup vs baseline: 2.8109x; 2.8109x over previous
#include <cuda_runtime.h>
#include <cuda_bf16.h>

#define N_NODES 50000
#define N_EDGES 800000
#define D 64
#define NBLK ((N_NODES + 255) / 256)   // 196

// ---------------------------------------------------------------------------
// Static device scratch (allocation-guard-legal).
// g_cnt zero at load; finalize_kernel re-zeroes it each run -> replay-safe.
// ---------------------------------------------------------------------------
__device__ int   g_cnt[N_NODES];
__device__ int   g_offs[N_NODES + 1];
__device__ int   g_cursor[N_NODES];
__device__ int   g_sorted[N_EDGES];
__device__ float g_Y[N_NODES * D];      // Y = feat @ W^T
__device__ int   g_blkSum[NBLK];
__device__ int   g_blkBase[NBLK];

// Side stream + events for graph-forked overlap (created at program init,
// no allocations inside kernel_launch).
static cudaStream_t g_side;
static cudaEvent_t  g_evFork, g_evJoin;
namespace {
struct _Init {
    _Init() {
        cudaStreamCreateWithFlags(&g_side, cudaStreamNonBlocking);
        cudaEventCreateWithFlags(&g_evFork, cudaEventDisableTiming);
        cudaEventCreateWithFlags(&g_evJoin, cudaEventDisableTiming);
    }
} _g_init;
}

// ---------------------------------------------------------------------------
// 1) Histogram of destination degrees (RED, no return)
// ---------------------------------------------------------------------------
__global__ __launch_bounds__(256) void hist_kernel(const int* __restrict__ dst,
                                                   int* __restrict__ cnt)
{
    int e = blockIdx.x * blockDim.x + threadIdx.x;
    if (e < N_EDGES) atomicAdd(&cnt[__ldg(dst + e)], 1);
}

// ---------------------------------------------------------------------------
// 2a) Per-block partial sums (coalesced, 196 blocks) -- R4-proven
// ---------------------------------------------------------------------------
__global__ __launch_bounds__(256) void partial_kernel(const int* __restrict__ cnt,
                                                      int* __restrict__ blkSum)
{
    __shared__ int sm[256];
    int idx = blockIdx.x * 256 + threadIdx.x;
    int v = (idx < N_NODES) ? __ldg(cnt + idx) : 0;
    sm[threadIdx.x] = v;
    __syncthreads();
    for (int off = 128; off > 0; off >>= 1) {
        if (threadIdx.x < off) sm[threadIdx.x] += sm[threadIdx.x + off];
        __syncthreads();
    }
    if (threadIdx.x == 0) blkSum[blockIdx.x] = sm[0];
}

// ---------------------------------------------------------------------------
// 2b) Exclusive scan of 196 block sums (1 block; tiny, coalesced)
// ---------------------------------------------------------------------------
__global__ __launch_bounds__(256) void scanbase_kernel(const int* __restrict__ blkSum,
                                                       int* __restrict__ blkBase)
{
    __shared__ int sm[256];
    int t = threadIdx.x;
    int v = (t < NBLK) ? __ldg(blkSum + t) : 0;
    sm[t] = v;
    __syncthreads();
    for (int off = 1; off < 256; off <<= 1) {
        int u = (t >= off) ? sm[t - off] : 0;
        __syncthreads();
        sm[t] += u;
        __syncthreads();
    }
    if (t < NBLK) blkBase[t] = sm[t] - v;   // exclusive
}

// ---------------------------------------------------------------------------
// 2c) Finalize offsets + cursors; re-zero cnt for next graph replay
// ---------------------------------------------------------------------------
__global__ __launch_bounds__(256) void finalize_kernel(
    int* __restrict__ cnt, const int* __restrict__ blkBase,
    int* __restrict__ offs, int* __restrict__ cursor)
{
    __shared__ int sm[256];
    int t = threadIdx.x;
    int idx = blockIdx.x * 256 + t;
    int c = (idx < N_NODES) ? cnt[idx] : 0;
    sm[t] = c;
    __syncthreads();
    for (int off = 1; off < 256; off <<= 1) {
        int u = (t >= off) ? sm[t - off] : 0;
        __syncthreads();
        sm[t] += u;
        __syncthreads();
    }
    int off = __ldg(blkBase + blockIdx.x) + sm[t] - c;   // exclusive prefix
    if (idx < N_NODES) {
        offs[idx]   = off;
        cursor[idx] = off;
        cnt[idx]    = 0;                                 // restore for replay
        if (idx == N_NODES - 1) offs[N_NODES] = off + c; // = N_EDGES
    }
}

// ---------------------------------------------------------------------------
// 3) Scatter src indices into dst-sorted order (R4-proven)
// ---------------------------------------------------------------------------
__global__ __launch_bounds__(256) void scatter_idx_kernel(
    const int* __restrict__ src, const int* __restrict__ dst,
    int* __restrict__ cursor, int* __restrict__ sorted)
{
    int e = blockIdx.x * blockDim.x + threadIdx.x;
    if (e >= N_EDGES) return;
    int d = __ldg(dst + e);
    int pos = atomicAdd(&cursor[d], 1);
    sorted[pos] = __ldg(src + e);
}

// ---------------------------------------------------------------------------
// 4) Y = feat @ W^T   (R2/R4-proven scalar-FFMA body, no epilogue extras)
// ---------------------------------------------------------------------------
#define GROWS 96

__global__ __launch_bounds__(GROWS) void gemm_y_kernel(
    const float4* __restrict__ feat, const float4* __restrict__ W,
    float4* __restrict__ Y)
{
    __shared__ float4 Wsm[64 * 16];       // Wsm[j*16 + kq] = W[j][4kq..4kq+3]
    __shared__ float4 tile[GROWS * 17];   // padded row stride

    const int tid  = threadIdx.x;
    const int row0 = blockIdx.x * GROWS;

    for (int i = tid; i < 64 * 16; i += GROWS) Wsm[i] = W[i];

    for (int i = tid; i < GROWS * 16; i += GROWS) {
        int r = i >> 4, c = i & 15;
        int gr = row0 + r;
        float4 v = make_float4(0.f, 0.f, 0.f, 0.f);
        if (gr < N_NODES) v = feat[gr * 16 + c];
        tile[r * 17 + c] = v;
    }
    __syncthreads();

    float acc[64];
#pragma unroll
    for (int j = 0; j < 64; j++) acc[j] = 0.f;

    for (int kq = 0; kq < 16; kq++) {           // NOT unrolled (I$)
        float4 v = tile[tid * 17 + kq];
#pragma unroll
        for (int j = 0; j < 64; j++) {          // broadcast LDS.128 of W
            float4 w = Wsm[j * 16 + kq];
            acc[j] += v.x * w.x + v.y * w.y + v.z * w.z + v.w * w.w;
        }
    }

    __syncthreads();
#pragma unroll
    for (int q = 0; q < 16; q++)
        tile[tid * 17 + q] =
            make_float4(acc[4 * q], acc[4 * q + 1], acc[4 * q + 2], acc[4 * q + 3]);
    __syncthreads();

    for (int i = tid; i < GROWS * 16; i += GROWS) {
        int r = i >> 4, c = i & 15;
        int gr = row0 + r;
        if (gr < N_NODES) Y[gr * 16 + c] = tile[r * 17 + c];
    }
}

// ---------------------------------------------------------------------------
// 5) Final gather: out[g] = (1+eps)*Y[g] + sum_{e in CSR[g]} Y[src_e] + b
//    (proven gather body @LTS cap, with the linear epilogue folded in)
// ---------------------------------------------------------------------------
__global__ __launch_bounds__(256) void gather_final_kernel(
    const float4* __restrict__ Y, const int* __restrict__ offs,
    const int* __restrict__ sorted, const float* __restrict__ eps,
    const float4* __restrict__ b4, float4* __restrict__ out)
{
    int g = (blockIdx.x * blockDim.x + threadIdx.x) >> 4;   // node
    int c = threadIdx.x & 15;
    if (g >= N_NODES) return;

    int beg = __ldg(offs + g);
    int end = __ldg(offs + g + 1);

    float4 a = make_float4(0.f, 0.f, 0.f, 0.f);
    int e = beg;
    for (; e + 4 <= end; e += 4) {
        int s0 = __ldg(sorted + e);
        int s1 = __ldg(sorted + e + 1);
        int s2 = __ldg(sorted + e + 2);
        int s3 = __ldg(sorted + e + 3);
        float4 f0 = Y[s0 * 16 + c];
        float4 f1 = Y[s1 * 16 + c];
        float4 f2 = Y[s2 * 16 + c];
        float4 f3 = Y[s3 * 16 + c];
        a.x += (f0.x + f1.x) + (f2.x + f3.x);
        a.y += (f0.y + f1.y) + (f2.y + f3.y);
        a.z += (f0.z + f1.z) + (f2.z + f3.z);
        a.w += (f0.w + f1.w) + (f2.w + f3.w);
    }
    for (; e < end; e++) {
        int s = __ldg(sorted + e);
        float4 f = Y[s * 16 + c];
        a.x += f.x; a.y += f.y; a.z += f.z; a.w += f.w;
    }

    float sc = 1.0f + __ldg(eps);
    float4 yg = Y[g * 16 + c];
    float4 bb = __ldg(b4 + c);
    a.x += sc * yg.x + bb.x;
    a.y += sc * yg.y + bb.y;
    a.z += sc * yg.z + bb.z;
    a.w += sc * yg.w + bb.w;
    out[g * 16 + c] = a;
}

// ---------------------------------------------------------------------------
// Launch: inputs per metadata order: feat, W, b, eps, src, dst
// Graph fork: CSR build (side stream) overlaps GEMM (main stream).
// ---------------------------------------------------------------------------
extern "C" void kernel_launch(void* const* d_in, const int* in_sizes, int n_in,
                              void* d_out, int out_size)
{
    const float4* feat = (const float4*)d_in[0];
    const float4* W    = (const float4*)d_in[1];
    const float4* b4   = (const float4*)d_in[2];
    const float*  eps  = (const float*)d_in[3];
    const int*    src  = (const int*)d_in[4];
    const int*    dst  = (const int*)d_in[5];
    float4*       out  = (float4*)d_out;

    int *cnt, *offs, *cursor, *sorted, *blkSum, *blkBase;
    float* Y;
    cudaGetSymbolAddress((void**)&cnt,     g_cnt);
    cudaGetSymbolAddress((void**)&offs,    g_offs);
    cudaGetSymbolAddress((void**)&cursor,  g_cursor);
    cudaGetSymbolAddress((void**)&sorted,  g_sorted);
    cudaGetSymbolAddress((void**)&Y,       g_Y);
    cudaGetSymbolAddress((void**)&blkSum,  g_blkSum);
    cudaGetSymbolAddress((void**)&blkBase, g_blkBase);

    const int EB = (N_EDGES + 255) / 256;

    // Fork: CSR build chain on side stream
    cudaEventRecord(g_evFork, 0);
    cudaStreamWaitEvent(g_side, g_evFork, 0);
    hist_kernel<<<EB, 256, 0, g_side>>>(dst, cnt);
    partial_kernel<<<NBLK, 256, 0, g_side>>>(cnt, blkSum);
    scanbase_kernel<<<1, 256, 0, g_side>>>(blkSum, blkBase);
    finalize_kernel<<<NBLK, 256, 0, g_side>>>(cnt, blkBase, offs, cursor);
    scatter_idx_kernel<<<EB, 256, 0, g_side>>>(src, dst, cursor, sorted);
    cudaEventRecord(g_evJoin, g_side);

    // Main stream: Y = feat @ W^T (overlaps with the CSR build)
    {
        int blocks = (N_NODES + GROWS - 1) / GROWS;
        gemm_y_kernel<<<blocks, GROWS>>>(feat, W, (float4*)Y);
    }

    // Join, then final gather writes out directly
    cudaStreamWaitEvent(0, g_evJoin, 0);
    {
        int threads = N_NODES * 16;
        gather_final_kernel<<<(threads + 255) / 256, 256>>>(
            (const float4*)Y, offs, sorted, eps, b4, out);
    }
}

// round 8
// speedup vs baseline: 2.8208x; 1.0035x over previous
#include <cuda_runtime.h>
#include <cuda_bf16.h>
#include <cuda_fp16.h>

#define N_NODES 50000
#define N_EDGES 800000
#define D 64
#define NBLK ((N_NODES + 255) / 256)   // 196

// ---------------------------------------------------------------------------
// Static device scratch (allocation-guard-legal).
// g_cnt zero at load; finalize_kernel re-zeroes it each run -> replay-safe.
// ---------------------------------------------------------------------------
__device__ int    g_cnt[N_NODES];
__device__ int    g_offs[N_NODES + 1];
__device__ int    g_cursor[N_NODES];
__device__ int    g_sorted[N_EDGES];
__device__ float  g_Y[N_NODES * D];            // Y = feat @ W^T (fp32)
__device__ __half g_Yh[N_NODES * D];           // fp16 copy for gather traffic
__device__ int    g_blkSum[NBLK];

// Side stream + events for graph-forked overlap (created at program init).
static cudaStream_t g_side;
static cudaEvent_t  g_evFork, g_evJoin;
namespace {
struct _Init {
    _Init() {
        cudaStreamCreateWithFlags(&g_side, cudaStreamNonBlocking);
        cudaEventCreateWithFlags(&g_evFork, cudaEventDisableTiming);
        cudaEventCreateWithFlags(&g_evJoin, cudaEventDisableTiming);
    }
} _g_init;
}

// ---------------------------------------------------------------------------
// 1) Histogram of destination degrees (RED, no return)
// ---------------------------------------------------------------------------
__global__ __launch_bounds__(256) void hist_kernel(const int* __restrict__ dst,
                                                   int* __restrict__ cnt)
{
    int e = blockIdx.x * blockDim.x + threadIdx.x;
    if (e < N_EDGES) atomicAdd(&cnt[__ldg(dst + e)], 1);
}

// ---------------------------------------------------------------------------
// 2a) Per-block partial sums (coalesced, 196 blocks)
// ---------------------------------------------------------------------------
__global__ __launch_bounds__(256) void partial_kernel(const int* __restrict__ cnt,
                                                      int* __restrict__ blkSum)
{
    __shared__ int sm[256];
    int idx = blockIdx.x * 256 + threadIdx.x;
    int v = (idx < N_NODES) ? __ldg(cnt + idx) : 0;
    sm[threadIdx.x] = v;
    __syncthreads();
    for (int off = 128; off > 0; off >>= 1) {
        if (threadIdx.x < off) sm[threadIdx.x] += sm[threadIdx.x + off];
        __syncthreads();
    }
    if (threadIdx.x == 0) blkSum[blockIdx.x] = sm[0];
}

// ---------------------------------------------------------------------------
// 2b) Finalize: inline block-base reduction over blkSum (replaces the
//     separate scanbase launch), local exclusive scan, write offs+cursor,
//     re-zero cnt for the next graph replay.
// ---------------------------------------------------------------------------
__global__ __launch_bounds__(256) void finalize_kernel(
    int* __restrict__ cnt, const int* __restrict__ blkSum,
    int* __restrict__ offs, int* __restrict__ cursor)
{
    __shared__ int sm[256];
    __shared__ int sbase[8];
    const int t = threadIdx.x;
    const int bid = blockIdx.x;

    // Inline base: sum of blkSum[0..bid) — 196 values, L2-resident
    int bv = (t < bid && t < NBLK) ? __ldg(blkSum + t) : 0;
#pragma unroll
    for (int o = 16; o > 0; o >>= 1) bv += __shfl_down_sync(~0u, bv, o);
    if ((t & 31) == 0) sbase[t >> 5] = bv;

    int idx = bid * 256 + t;
    int c = (idx < N_NODES) ? cnt[idx] : 0;
    sm[t] = c;
    __syncthreads();

    int base = sbase[0] + sbase[1] + sbase[2] + sbase[3] +
               sbase[4] + sbase[5] + sbase[6] + sbase[7];

    for (int off = 1; off < 256; off <<= 1) {
        int u = (t >= off) ? sm[t - off] : 0;
        __syncthreads();
        sm[t] += u;
        __syncthreads();
    }
    int off = base + sm[t] - c;   // exclusive prefix
    if (idx < N_NODES) {
        offs[idx]   = off;
        cursor[idx] = off;
        cnt[idx]    = 0;                                 // restore for replay
        if (idx == N_NODES - 1) offs[N_NODES] = off + c; // = N_EDGES
    }
}

// ---------------------------------------------------------------------------
// 3) Scatter src indices into dst-sorted order (proven)
// ---------------------------------------------------------------------------
__global__ __launch_bounds__(256) void scatter_idx_kernel(
    const int* __restrict__ src, const int* __restrict__ dst,
    int* __restrict__ cursor, int* __restrict__ sorted)
{
    int e = blockIdx.x * blockDim.x + threadIdx.x;
    if (e >= N_EDGES) return;
    int d = __ldg(dst + e);
    int pos = atomicAdd(&cursor[d], 1);
    sorted[pos] = __ldg(src + e);
}

// ---------------------------------------------------------------------------
// 4) Y = feat @ W^T  (proven scalar-FFMA body) + fp16 copy for the gather
// ---------------------------------------------------------------------------
#define GROWS 96

__global__ __launch_bounds__(GROWS) void gemm_y_kernel(
    const float4* __restrict__ feat, const float4* __restrict__ W,
    float4* __restrict__ Y, uint2* __restrict__ Yh)
{
    __shared__ float4 Wsm[64 * 16];       // Wsm[j*16 + kq] = W[j][4kq..4kq+3]
    __shared__ float4 tile[GROWS * 17];   // padded row stride

    const int tid  = threadIdx.x;
    const int row0 = blockIdx.x * GROWS;

    for (int i = tid; i < 64 * 16; i += GROWS) Wsm[i] = W[i];

    for (int i = tid; i < GROWS * 16; i += GROWS) {
        int r = i >> 4, c = i & 15;
        int gr = row0 + r;
        float4 v = make_float4(0.f, 0.f, 0.f, 0.f);
        if (gr < N_NODES) v = feat[gr * 16 + c];
        tile[r * 17 + c] = v;
    }
    __syncthreads();

    float acc[64];
#pragma unroll
    for (int j = 0; j < 64; j++) acc[j] = 0.f;

    for (int kq = 0; kq < 16; kq++) {           // NOT unrolled (I$)
        float4 v = tile[tid * 17 + kq];
#pragma unroll
        for (int j = 0; j < 64; j++) {          // broadcast LDS.128 of W
            float4 w = Wsm[j * 16 + kq];
            acc[j] += v.x * w.x + v.y * w.y + v.z * w.z + v.w * w.w;
        }
    }

    __syncthreads();
#pragma unroll
    for (int q = 0; q < 16; q++)
        tile[tid * 17 + q] =
            make_float4(acc[4 * q], acc[4 * q + 1], acc[4 * q + 2], acc[4 * q + 3]);
    __syncthreads();

    for (int i = tid; i < GROWS * 16; i += GROWS) {
        int r = i >> 4, c = i & 15;
        int gr = row0 + r;
        if (gr < N_NODES) {
            float4 v = tile[r * 17 + c];
            Y[gr * 16 + c] = v;
            __half2 h0 = __floats2half2_rn(v.x, v.y);
            __half2 h1 = __floats2half2_rn(v.z, v.w);
            uint2 hp;
            hp.x = *(unsigned int*)&h0;
            hp.y = *(unsigned int*)&h1;
            Yh[gr * 16 + c] = hp;   // 8B per lane-slot, 128B per node row
        }
    }
}

// ---------------------------------------------------------------------------
// 5) Final gather: out[g] = (1+eps)*Y[g] + sum_e Yh[src_e] + b
//    Neighbor reads in fp16 (halved traffic), accumulation + residual fp32.
// ---------------------------------------------------------------------------
__global__ __launch_bounds__(256) void gather_final_kernel(
    const float4* __restrict__ Y, const uint2* __restrict__ Yh,
    const int* __restrict__ offs, const int* __restrict__ sorted,
    const float* __restrict__ eps, const float4* __restrict__ b4,
    float4* __restrict__ out)
{
    int g = (blockIdx.x * blockDim.x + threadIdx.x) >> 4;   // node
    int c = threadIdx.x & 15;
    if (g >= N_NODES) return;

    int beg = __ldg(offs + g);
    int end = __ldg(offs + g + 1);

    float4 a = make_float4(0.f, 0.f, 0.f, 0.f);
    int e = beg;
    for (; e + 4 <= end; e += 4) {
        int s0 = __ldg(sorted + e);
        int s1 = __ldg(sorted + e + 1);
        int s2 = __ldg(sorted + e + 2);
        int s3 = __ldg(sorted + e + 3);
        uint2 p0 = Yh[s0 * 16 + c];
        uint2 p1 = Yh[s1 * 16 + c];
        uint2 p2 = Yh[s2 * 16 + c];
        uint2 p3 = Yh[s3 * 16 + c];
        float2 f;
        f = __half22float2(*(__half2*)&p0.x); a.x += f.x; a.y += f.y;
        f = __half22float2(*(__half2*)&p0.y); a.z += f.x; a.w += f.y;
        f = __half22float2(*(__half2*)&p1.x); a.x += f.x; a.y += f.y;
        f = __half22float2(*(__half2*)&p1.y); a.z += f.x; a.w += f.y;
        f = __half22float2(*(__half2*)&p2.x); a.x += f.x; a.y += f.y;
        f = __half22float2(*(__half2*)&p2.y); a.z += f.x; a.w += f.y;
        f = __half22float2(*(__half2*)&p3.x); a.x += f.x; a.y += f.y;
        f = __half22float2(*(__half2*)&p3.y); a.z += f.x; a.w += f.y;
    }
    for (; e < end; e++) {
        int s = __ldg(sorted + e);
        uint2 p = Yh[s * 16 + c];
        float2 f;
        f = __half22float2(*(__half2*)&p.x); a.x += f.x; a.y += f.y;
        f = __half22float2(*(__half2*)&p.y); a.z += f.x; a.w += f.y;
    }

    float sc = 1.0f + __ldg(eps);
    float4 yg = Y[g * 16 + c];             // residual stays fp32
    float4 bb = __ldg(b4 + c);
    a.x += sc * yg.x + bb.x;
    a.y += sc * yg.y + bb.y;
    a.z += sc * yg.z + bb.z;
    a.w += sc * yg.w + bb.w;
    out[g * 16 + c] = a;
}

// ---------------------------------------------------------------------------
// Launch: inputs per metadata order: feat, W, b, eps, src, dst
// Fork: CSR build (side stream) overlaps GEMM (main stream).
// ---------------------------------------------------------------------------
extern "C" void kernel_launch(void* const* d_in, const int* in_sizes, int n_in,
                              void* d_out, int out_size)
{
    const float4* feat = (const float4*)d_in[0];
    const float4* W    = (const float4*)d_in[1];
    const float4* b4   = (const float4*)d_in[2];
    const float*  eps  = (const float*)d_in[3];
    const int*    src  = (const int*)d_in[4];
    const int*    dst  = (const int*)d_in[5];
    float4*       out  = (float4*)d_out;

    int *cnt, *offs, *cursor, *sorted, *blkSum;
    float* Y;
    __half* Yh;
    cudaGetSymbolAddress((void**)&cnt,    g_cnt);
    cudaGetSymbolAddress((void**)&offs,   g_offs);
    cudaGetSymbolAddress((void**)&cursor, g_cursor);
    cudaGetSymbolAddress((void**)&sorted, g_sorted);
    cudaGetSymbolAddress((void**)&Y,      g_Y);
    cudaGetSymbolAddress((void**)&Yh,     g_Yh);
    cudaGetSymbolAddress((void**)&blkSum, g_blkSum);

    const int EB = (N_EDGES + 255) / 256;

    // Fork: CSR build chain on side stream
    cudaEventRecord(g_evFork, 0);
    cudaStreamWaitEvent(g_side, g_evFork, 0);
    hist_kernel<<<EB, 256, 0, g_side>>>(dst, cnt);
    partial_kernel<<<NBLK, 256, 0, g_side>>>(cnt, blkSum);
    finalize_kernel<<<NBLK, 256, 0, g_side>>>(cnt, blkSum, offs, cursor);
    scatter_idx_kernel<<<EB, 256, 0, g_side>>>(src, dst, cursor, sorted);
    cudaEventRecord(g_evJoin, g_side);

    // Main stream: Y = feat @ W^T (+ fp16 copy), overlaps the CSR build
    {
        int blocks = (N_NODES + GROWS - 1) / GROWS;
        gemm_y_kernel<<<blocks, GROWS>>>(feat, W, (float4*)Y, (uint2*)Yh);
    }

    // Join, then final gather writes out directly
    cudaStreamWaitEvent(0, g_evJoin, 0);
    {
        int threads = N_NODES * 16;
        gather_final_kernel<<<(threads + 255) / 256, 256>>>(
            (const float4*)Y, (const uint2*)Yh, offs, sorted, eps, b4, out);
    }
}